// round 3
// baseline (speedup 1.0000x reference)
#include <cuda_runtime.h>

#define CELL_N 76
#define DRUG_N 764
#define TOT_N  840
#define BATCH  4096
#define NPROT  15970
#define KSPLIT 16
#define KCHUNK 512   // 8192 / KSPLIT

// fused conv smem layout (floats)
#define T_STRIDE 136
#define T_ELEMS  (70 * T_STRIDE)          // 9520
#define P_STRIDE 68
#define P_CH     (34 * P_STRIDE)          // 2312
#define P_ELEMS  (4 * P_CH)               // 9248
#define CONV_SMEM_BYTES ((T_ELEMS + P_ELEMS) * 4)   // 75072

// ---------------- scratch (device globals; no allocs allowed) ----------------
__device__ float g_pool2[TOT_N * 8 * 32 * 32];   // after conv2+relu+pool
__device__ float g_fcp  [KSPLIT * TOT_N * 64];   // FC partials (K-split)
__device__ float g_item [TOT_N * 64];            // FC out, standardized in place
__device__ float g_inter[TOT_N * 128];           // interact output
__device__ float g_emb  [TOT_N * 64];            // agg output (cell 0..75, drug 76..839)
__device__ float g_normsq[TOT_N];                // per-row |emb|^2
__device__ float g_U    [CELL_N * 128];          // comb_w^T @ cell_emb[c]
__device__ float g_tablesq[NPROT];               // per-protein-row |.|^2
__device__ float g_part [32];                    // item_reg block partials (deterministic)

// ---------------- per-protein squared norms ----------------
__global__ void k_tablesq(const float* __restrict__ table) {
    int warp = (blockIdx.x * blockDim.x + threadIdx.x) >> 5;
    int lane = threadIdx.x & 31;
    if (warp >= NPROT) return;
    const float* r = table + warp * 64;
    float a = r[lane], b = r[lane + 32];
    float s = a * a + b * b;
    #pragma unroll
    for (int o = 16; o; o >>= 1) s += __shfl_down_sync(0xffffffffu, s, o);
    if (lane == 0) g_tablesq[warp] = s;
}

// ---------------- fused conv1+pool1+conv2+pool2 ----------------
// grid = 1680 (one block per (image, half)); block = 256; dynamic smem.
// Input tile T: 70 rows x 136 cols, T[u][t] = input[64h-3+u][t-3] (0-padded).
// pool1 tile P: 4ch x 34 x 68, P[c][r][cc] = pool1[c][32h-1+r][cc-1] (0 if OOB).
__global__ void __launch_bounds__(256, 3) k_conv12(
        const float* __restrict__ cell_pre, const float* __restrict__ drug_pre,
        const float* __restrict__ w1, const float* __restrict__ b1,
        const float* __restrict__ w2, const float* __restrict__ b2) {
    extern __shared__ float sm[];
    float* T = sm;
    float* P = sm + T_ELEMS;

    int blk = blockIdx.x;
    int half = blk & 1;
    const float* x;
    int gn;
    if (blk < 2 * CELL_N) { int n = blk >> 1; x = cell_pre + n * 16384; gn = n; }
    else { int n = (blk - 2 * CELL_N) >> 1; x = drug_pre + n * 16384; gn = CELL_N + n; }
    int tid = threadIdx.x;

    // conv1 weights in registers (const-indexed)
    float w1r[36];
    #pragma unroll
    for (int i = 0; i < 36; i++) w1r[i] = w1[i];
    float b1r[4] = { b1[0], b1[1], b1[2], b1[3] };

    // load input tile
    int y0 = 64 * half - 3;
    for (int idx = tid; idx < T_ELEMS; idx += 256) {
        int u = idx / T_STRIDE, t = idx - u * T_STRIDE;
        int y = y0 + u, xx = t - 3;
        T[idx] = ((unsigned)y < 128u && (unsigned)xx < 128u) ? x[y * 128 + xx] : 0.f;
    }
    __syncthreads();

    // conv1 + relu + pool -> P.  tasks: (r in [0,34)) x (p in [0,33)), 2 cols each
    for (int task = tid; task < 34 * 33; task += 256) {
        int r = task / 33, p = task - r * 33;
        float pt[4][6];
        #pragma unroll
        for (int rr = 0; rr < 4; rr++) {
            const float* base = &T[(2 * r + rr) * T_STRIDE + 4 * p];
            float4 a = *(const float4*)base;
            float2 bq = *(const float2*)(base + 4);
            pt[rr][0] = a.x; pt[rr][1] = a.y; pt[rr][2] = a.z;
            pt[rr][3] = a.w; pt[rr][4] = bq.x; pt[rr][5] = bq.y;
        }
        int rr_log = 32 * half - 1 + r;
        bool rowok = (unsigned)rr_log < 64u;
        #pragma unroll
        for (int cp = 0; cp < 2; cp++) {
            int cc = 2 * p + cp;
            bool ok = rowok && ((unsigned)(cc - 1) < 64u);
            #pragma unroll
            for (int oc = 0; oc < 4; oc++) {
                float q00 = b1r[oc], q01 = b1r[oc], q10 = b1r[oc], q11 = b1r[oc];
                #pragma unroll
                for (int dy = 0; dy < 3; dy++)
                #pragma unroll
                for (int dx = 0; dx < 3; dx++) {
                    float wv = w1r[oc * 9 + dy * 3 + dx];
                    q00 += pt[dy    ][2 * cp + dx    ] * wv;
                    q01 += pt[dy    ][2 * cp + dx + 1] * wv;
                    q10 += pt[dy + 1][2 * cp + dx    ] * wv;
                    q11 += pt[dy + 1][2 * cp + dx + 1] * wv;
                }
                float m = fmaxf(fmaxf(q00, q01), fmaxf(q10, q11));
                P[oc * P_CH + r * P_STRIDE + cc] = ok ? fmaxf(m, 0.f) : 0.f;
            }
        }
    }
    __syncthreads();

    // conv2 + relu + pool -> g_pool2.  oc fixed per warp; tasks: 16 oy x 16 ox-pairs
    int oc = tid >> 5, lane = tid & 31;
    float w2r[36];
    #pragma unroll
    for (int i = 0; i < 36; i++) w2r[i] = w2[oc * 36 + i];
    float b2s = b2[oc];
    #pragma unroll
    for (int i = 0; i < 8; i++) {
        int pos = lane + i * 32;
        int oy = pos >> 4, oxp = pos & 15;
        float q[2][4];
        #pragma unroll
        for (int pr = 0; pr < 2; pr++)
            #pragma unroll
            for (int k = 0; k < 4; k++) q[pr][k] = b2s;
        #pragma unroll
        for (int c = 0; c < 4; c++) {
            float pt[4][6];
            #pragma unroll
            for (int rr = 0; rr < 4; rr++) {
                const float* base = &P[c * P_CH + (2 * oy + rr) * P_STRIDE + 4 * oxp];
                float4 a = *(const float4*)base;
                float2 bq = *(const float2*)(base + 4);
                pt[rr][0] = a.x; pt[rr][1] = a.y; pt[rr][2] = a.z;
                pt[rr][3] = a.w; pt[rr][4] = bq.x; pt[rr][5] = bq.y;
            }
            #pragma unroll
            for (int dy = 0; dy < 3; dy++)
            #pragma unroll
            for (int dx = 0; dx < 3; dx++) {
                float wv = w2r[c * 9 + dy * 3 + dx];
                #pragma unroll
                for (int pr = 0; pr < 2; pr++) {
                    q[pr][0] += pt[dy    ][2 * pr + dx    ] * wv;
                    q[pr][1] += pt[dy    ][2 * pr + dx + 1] * wv;
                    q[pr][2] += pt[dy + 1][2 * pr + dx    ] * wv;
                    q[pr][3] += pt[dy + 1][2 * pr + dx + 1] * wv;
                }
            }
        }
        float2 outv;
        float m0 = fmaxf(fmaxf(q[0][0], q[0][1]), fmaxf(q[0][2], q[0][3]));
        float m1 = fmaxf(fmaxf(q[1][0], q[1][1]), fmaxf(q[1][2], q[1][3]));
        outv.x = fmaxf(m0, 0.f);
        outv.y = fmaxf(m1, 0.f);
        *(float2*)&g_pool2[((gn * 8 + oc) * 32 + 16 * half + oy) * 32 + 2 * oxp] = outv;
    }
}

// ---------------- FC as tiled GEMM with K-split ----------------
__global__ void __launch_bounds__(256) k_fc(const float* __restrict__ W) {
    int m0 = blockIdx.x * 32;
    int kb = blockIdx.y;
    int k0 = kb * KCHUNK;
    __shared__ float Xs[32][64];
    __shared__ float Ws[64][68];
    int tid = threadIdx.x;
    int tm = tid >> 5, tn = tid & 31;
    float acc[4][2] = {};
    for (int kt = 0; kt < KCHUNK; kt += 64) {
        #pragma unroll
        for (int i = 0; i < 8; i++) {
            int idx = tid + i * 256;
            int r = idx >> 6, c = idx & 63;
            int m = m0 + r;
            Xs[r][c] = (m < TOT_N) ? g_pool2[m * 8192 + k0 + kt + c] : 0.f;
        }
        #pragma unroll
        for (int i = 0; i < 16; i++) {
            int idx = tid + i * 256;
            int j = idx >> 6, c = idx & 63;
            Ws[j][c] = W[j * 8192 + k0 + kt + c];
        }
        __syncthreads();
        #pragma unroll
        for (int kk = 0; kk < 64; kk += 4) {
            float4 w0 = *(const float4*)&Ws[tn     ][kk];
            float4 w1 = *(const float4*)&Ws[tn + 32][kk];
            #pragma unroll
            for (int r = 0; r < 4; r++) {
                float4 xv = *(const float4*)&Xs[tm * 4 + r][kk];
                acc[r][0] += xv.x * w0.x + xv.y * w0.y + xv.z * w0.z + xv.w * w0.w;
                acc[r][1] += xv.x * w1.x + xv.y * w1.y + xv.z * w1.z + xv.w * w1.w;
            }
        }
        __syncthreads();
    }
    #pragma unroll
    for (int r = 0; r < 4; r++) {
        int m = m0 + tm * 4 + r;
        if (m < TOT_N) {
            g_fcp[(kb * TOT_N + m) * 64 + tn     ] = acc[r][0];
            g_fcp[(kb * TOT_N + m) * 64 + tn + 32] = acc[r][1];
        }
    }
}

// reduce K-split partials + bias -> g_item
__global__ void k_fcred(const float* __restrict__ b) {
    int idx = blockIdx.x * blockDim.x + threadIdx.x;
    if (idx >= TOT_N * 64) return;
    float s = b[idx & 63];
    #pragma unroll
    for (int kb = 0; kb < KSPLIT; kb++) s += g_fcp[kb * TOT_N * 64 + idx];
    g_item[idx] = s;
}

// ---------------- standardize per feature over a group (ddof=1) ----------------
// grid = 2, block = 1024 (feature j = tid&63, slice q = tid>>6: 16 slices)
__global__ void __launch_bounds__(1024) k_std() {
    int base = blockIdx.x ? CELL_N * 64 : 0;
    int N    = blockIdx.x ? DRUG_N : CELL_N;
    __shared__ float red[1024];
    __shared__ float mv[64];
    __shared__ float sv[64];
    float* x = g_item + base;
    int tid = threadIdx.x;
    int j = tid & 63, q = tid >> 6;
    float s = 0.f;
    for (int n = q; n < N; n += 16) s += x[n * 64 + j];
    red[tid] = s;
    __syncthreads();
    if (tid < 64) {
        float t = 0.f;
        #pragma unroll
        for (int k = 0; k < 16; k++) t += red[tid + 64 * k];
        mv[tid] = t / (float)N;
    }
    __syncthreads();
    float mean = mv[j];
    float ss = 0.f;
    for (int n = q; n < N; n += 16) { float d = x[n * 64 + j] - mean; ss += d * d; }
    __syncthreads();
    red[tid] = ss;
    __syncthreads();
    if (tid < 64) {
        float t = 0.f;
        #pragma unroll
        for (int k = 0; k < 16; k++) t += red[tid + 64 * k];
        sv[tid] = rsqrtf(t / (float)(N - 1));
    }
    __syncthreads();
    float inv = sv[j];
    for (int n = q; n < N; n += 16) x[n * 64 + j] = (x[n * 64 + j] - mean) * inv;
}

// ---------------- interact (merged cell+drug): attention over 128 rows ----------------
// grid = 1680, block = 128
__global__ void k_interact(const int* __restrict__ cell_nbr, const int* __restrict__ drug_nbr,
                           const float* __restrict__ table) {
    int blk = blockIdx.x;
    const int* nbr;
    int nh, item_base, inter_base;
    if (blk < 2 * CELL_N) { nbr = cell_nbr; nh = blk; item_base = 0; inter_base = 0; }
    else { nbr = drug_nbr; nh = blk - 2 * CELL_N; item_base = CELL_N * 64; inter_base = CELL_N * 128; }
    int n = nh >> 1, h = nh & 1;
    __shared__ float rows[128 * 65];
    __shared__ float it[64];
    __shared__ int   idxs[128];
    __shared__ float sc[128];
    __shared__ float tmp[128];
    int tid = threadIdx.x;
    idxs[tid] = nbr[nh * 128 + tid];
    if (tid < 64) it[tid] = g_item[item_base + n * 64 + tid];
    __syncthreads();
    for (int e = tid; e < 128 * 64; e += 128) {
        int k = e >> 6, d = e & 63;
        rows[k * 65 + d] = table[idxs[k] * 64 + d];
    }
    __syncthreads();
    float s = 0.f;
    #pragma unroll 8
    for (int d = 0; d < 64; d++) s += rows[tid * 65 + d] * it[d];
    tmp[tid] = s;
    __syncthreads();
    #pragma unroll
    for (int off = 64; off; off >>= 1) {
        if (tid < off) tmp[tid] = fmaxf(tmp[tid], tmp[tid + off]);
        __syncthreads();
    }
    float mx = tmp[0];
    __syncthreads();
    float e = expf(s - mx);
    sc[tid] = e;
    tmp[tid] = e;
    __syncthreads();
    #pragma unroll
    for (int off = 64; off; off >>= 1) {
        if (tid < off) tmp[tid] += tmp[tid + off];
        __syncthreads();
    }
    float inv = 1.f / tmp[0];
    if (tid < 64) {
        float o = 0.f;
        #pragma unroll 8
        for (int k = 0; k < 128; k++) o += sc[k] * rows[k * 65 + tid];
        g_inter[inter_base + n * 128 + h * 64 + tid] = o * inv;
    }
}

// ---------------- agg + normsq + (cells) U ----------------
// grid = TOT_N, block = 128
__global__ void k_agg(const float* __restrict__ W, const float* __restrict__ b,
                      const float* __restrict__ combw) {
    int n = blockIdx.x;
    __shared__ float xr[128];
    __shared__ float e[64];
    __shared__ float red[64];
    int tid = threadIdx.x;
    xr[tid] = g_inter[n * 128 + tid];
    __syncthreads();
    if (tid < 64) {
        float s = b[tid];
        #pragma unroll 8
        for (int t = 0; t < 128; t++) s += W[tid * 128 + t] * xr[t];
        g_emb[n * 64 + tid] = s;
        e[tid] = s;
        red[tid] = s * s;
    }
    __syncthreads();
    if (tid < 32) {
        float v = red[tid] + red[tid + 32];
        #pragma unroll
        for (int o = 16; o; o >>= 1) v += __shfl_down_sync(0xffffffffu, v, o);
        if (tid == 0) g_normsq[n] = v;
    }
    if (n < CELL_N) {
        float s = 0.f;
        #pragma unroll 8
        for (int j = 0; j < 64; j++) s += combw[j * 128 + tid] * e[j];
        g_U[n * 128 + tid] = s;
    }
}

// ---------------- per-batch score + item_reg partials (deterministic) ----------------
// grid = 32, block = 128
__global__ void k_score(const int* __restrict__ data, float* __restrict__ out) {
    int bidx = blockIdx.x * blockDim.x + threadIdx.x;
    float reg = 0.f;
    if (bidx < BATCH) {
        int c  = data[3 * bidx];
        int d1 = data[3 * bidx + 1];
        int d2 = data[3 * bidx + 2];
        const float* e1 = g_emb + (CELL_N + d1) * 64;
        const float* e2 = g_emb + (CELL_N + d2) * 64;
        const float* u  = g_U + c * 128;
        float s = 0.f;
        #pragma unroll 8
        for (int t = 0; t < 64; t++) {
            float a = e1[t], bb = e2[t];
            s += a * u[t] + bb * u[64 + t] - a * bb;
        }
        out[bidx] = s;
        reg = 0.5f * (g_normsq[c] + g_normsq[CELL_N + d1] + g_normsq[CELL_N + d2]);
    }
    __shared__ float red[128];
    red[threadIdx.x] = reg;
    __syncthreads();
    #pragma unroll
    for (int off = 64; off; off >>= 1) {
        if (threadIdx.x < off) red[threadIdx.x] += red[threadIdx.x + off];
        __syncthreads();
    }
    if (threadIdx.x == 0) g_part[blockIdx.x] = red[0];
}

// ---------------- node_reg + loss ----------------
// grid = 1, block = 256
__global__ void k_loss(const int* __restrict__ data, const int* __restrict__ cell_nbr,
                       const int* __restrict__ drug_nbr, float* __restrict__ out, int loss_idx) {
    __shared__ float red[256];
    int tid = threadIdx.x;
    float s = 0.f;
    for (int e = tid; e < 1536; e += 256) {
        int set = e >> 8, off = e & 255;
        int hop = set / 3, which = set - hop * 3;
        int nodeidx = data[hop * 3 + which];
        int p = (which == 0) ? cell_nbr[nodeidx * 256 + off] : drug_nbr[nodeidx * 256 + off];
        s += g_tablesq[p];
    }
    red[tid] = s;
    __syncthreads();
    #pragma unroll
    for (int off = 128; off; off >>= 1) {
        if (tid < off) red[tid] += red[tid + off];
        __syncthreads();
    }
    if (tid == 0) {
        float item_reg = 0.f;
        #pragma unroll
        for (int i = 0; i < 32; i++) item_reg += g_part[i];
        out[loss_idx] = 1e-6f * (item_reg + 0.5f * red[0]) / (float)BATCH;
    }
}

// ---------------- launch ----------------
extern "C" void kernel_launch(void* const* d_in, const int* in_sizes, int n_in,
                              void* d_out, int out_size) {
    const int*   data     = (const int*)  d_in[0];
    const int*   cell_nbr = (const int*)  d_in[1];
    const int*   drug_nbr = (const int*)  d_in[2];
    const float* table    = (const float*)d_in[3];
    const float* cell_pre = (const float*)d_in[4];
    const float* drug_pre = (const float*)d_in[5];
    const float* c1w      = (const float*)d_in[6];
    const float* c1b      = (const float*)d_in[7];
    const float* c2w      = (const float*)d_in[8];
    const float* c2b      = (const float*)d_in[9];
    const float* ow       = (const float*)d_in[10];
    const float* ob       = (const float*)d_in[11];
    const float* aw       = (const float*)d_in[12];
    const float* ab       = (const float*)d_in[13];
    const float* cw       = (const float*)d_in[14];
    float* out = (float*)d_out;

    cudaFuncSetAttribute(k_conv12, cudaFuncAttributeMaxDynamicSharedMemorySize, CONV_SMEM_BYTES);

    k_tablesq<<<(NPROT * 32 + 255) / 256, 256>>>(table);

    k_conv12<<<TOT_N * 2, 256, CONV_SMEM_BYTES>>>(cell_pre, drug_pre, c1w, c1b, c2w, c2b);

    dim3 fcg(27, KSPLIT);
    k_fc<<<fcg, 256>>>(ow);
    k_fcred<<<(TOT_N * 64 + 255) / 256, 256>>>(ob);

    k_std<<<2, 1024>>>();

    k_interact<<<TOT_N * 2, 128>>>(cell_nbr, drug_nbr, table);

    k_agg<<<TOT_N, 128>>>(aw, ab, cw);
    k_score<<<32, 128>>>(data, out);
    k_loss<<<1, 256>>>(data, cell_nbr, drug_nbr, out, out_size - 1);
}

// round 4
// speedup vs baseline: 1.1356x; 1.1356x over previous
#include <cuda_runtime.h>

#define CELL_N 76
#define DRUG_N 764
#define TOT_N  840
#define BATCH  4096
#define NPROT  15970
#define KSPLIT 8
#define KCHUNK 1024  // 8192 / KSPLIT

typedef unsigned long long ull;

// packed f32x2 helpers
#define PACKB(p, x) do { unsigned _u = __float_as_uint(x); \
    asm("mov.b64 %0, {%1, %2};" : "=l"(p) : "r"(_u), "r"(_u)); } while (0)
#define PACK2(p, x, y) do { unsigned _ux = __float_as_uint(x), _uy = __float_as_uint(y); \
    asm("mov.b64 %0, {%1, %2};" : "=l"(p) : "r"(_ux), "r"(_uy)); } while (0)
#define FMA2(d, a, b) asm("fma.rn.f32x2 %0, %1, %2, %0;" : "+l"(d) : "l"(a), "l"(b))
#define UNPK(lo, hi, p) do { unsigned _ul, _uh; \
    asm("mov.b64 {%0, %1}, %2;" : "=r"(_ul), "=r"(_uh) : "l"(p)); \
    lo = __uint_as_float(_ul); hi = __uint_as_float(_uh); } while (0)

// ---------------- scratch (device globals; no allocs allowed) ----------------
__device__ float g_pool1[TOT_N * 4 * 64 * 64];   // after conv1+relu+pool
__device__ float g_pool2[TOT_N * 8 * 32 * 32];   // after conv2+relu+pool
__device__ float g_fcp  [KSPLIT * TOT_N * 64];   // FC partials (K-split)
__device__ float g_item [TOT_N * 64];            // FC out, standardized in place
__device__ float g_inter[TOT_N * 128];           // interact output
__device__ float g_emb  [TOT_N * 64];            // agg output
__device__ float g_normsq[TOT_N];                // per-row |emb|^2
__device__ float g_U    [CELL_N * 128];          // comb_w^T @ cell_emb[c]
__device__ float g_tablesq[NPROT];               // per-protein-row |.|^2
__device__ float g_part [32];                    // item_reg block partials

// ---------------- per-protein squared norms ----------------
__global__ void k_tablesq(const float* __restrict__ table) {
    int warp = (blockIdx.x * blockDim.x + threadIdx.x) >> 5;
    int lane = threadIdx.x & 31;
    if (warp >= NPROT) return;
    const float* r = table + warp * 64;
    float a = r[lane], b = r[lane + 32];
    float s = a * a + b * b;
    #pragma unroll
    for (int o = 16; o; o >>= 1) s += __shfl_down_sync(0xffffffffu, s, o);
    if (lane == 0) g_tablesq[warp] = s;
}

// ---------------- conv1 (1->4, 3x3 SAME) + relu + 2x2 maxpool ----------------
// grid = N*2 (half image rows per block), block = 256 (R2 version, proven)
__global__ void __launch_bounds__(256) k_conv1(
        const float* __restrict__ x, const float* __restrict__ w,
        const float* __restrict__ b, int obase) {
    int n = blockIdx.x >> 1, half = blockIdx.x & 1;
    __shared__ float tile[66 * 130];
    int tid = threadIdx.x;
    float wr[36];
    #pragma unroll
    for (int i = 0; i < 36; i++) wr[i] = w[i];
    float bb[4] = { b[0], b[1], b[2], b[3] };
    int row0 = half * 64 - 1;
    const float* xn = x + n * 128 * 128;
    for (int idx = tid; idx < 66 * 130; idx += 256) {
        int r = idx / 130, c = idx - r * 130;
        int y = row0 + r, xx = c - 1;
        tile[idx] = (y >= 0 && y < 128 && (unsigned)xx < 128u) ? xn[y * 128 + xx] : 0.f;
    }
    __syncthreads();
    #pragma unroll
    for (int i = 0; i < 8; i++) {
        int pos = tid + i * 256;
        int oy = pos >> 6, ox = pos & 63;
        float p[4][4];
        #pragma unroll
        for (int r = 0; r < 4; r++) {
            const float2* s = (const float2*)&tile[(2 * oy + r) * 130 + 2 * ox];
            float2 a = s[0], d = s[1];
            p[r][0] = a.x; p[r][1] = a.y; p[r][2] = d.x; p[r][3] = d.y;
        }
        #pragma unroll
        for (int oc = 0; oc < 4; oc++) {
            float q00 = bb[oc], q01 = bb[oc], q10 = bb[oc], q11 = bb[oc];
            #pragma unroll
            for (int dy = 0; dy < 3; dy++)
            #pragma unroll
            for (int dx = 0; dx < 3; dx++) {
                float wv = wr[oc * 9 + dy * 3 + dx];
                q00 += p[dy    ][dx    ] * wv;
                q01 += p[dy    ][dx + 1] * wv;
                q10 += p[dy + 1][dx    ] * wv;
                q11 += p[dy + 1][dx + 1] * wv;
            }
            float m = fmaxf(fmaxf(q00, q01), fmaxf(q10, q11));
            g_pool1[obase + ((n * 4 + oc) * 64 + half * 32 + oy) * 64 + ox] = fmaxf(m, 0.f);
        }
    }
}

// ---------------- conv2 (4->8) + relu + pool, f32x2 over oc-pairs ----------------
// grid = TOT_N*2, block = 256. Thread: ocpair = tid>>6 (2 ocs), 4 tasks of
// 2 pooled outputs each. Weights packed (oc_even, oc_odd) in smem -> LDS.64.
#define C2_STR 68
#define C2_CH  (34 * C2_STR)
__global__ void __launch_bounds__(256) k_conv2(
        const float* __restrict__ w, const float* __restrict__ b) {
    int n = blockIdx.x >> 1, half = blockIdx.x & 1;
    __shared__ float tile[4 * C2_CH];
    __shared__ float2 wp[4][36];     // [ocpair][tap]
    __shared__ float2 bpair[4];
    int tid = threadIdx.x;
    int row0 = half * 32 - 1;
    for (int idx = tid; idx < 4 * 34 * 66; idx += 256) {
        int c = idx / (34 * 66), rem = idx - c * 34 * 66;
        int r = rem / 66, cc = rem - r * 66;
        int y = row0 + r, xx = cc - 1;
        tile[c * C2_CH + r * C2_STR + cc] =
            ((unsigned)y < 64u && (unsigned)xx < 64u)
          ? g_pool1[((n * 4 + c) * 64 + y) * 64 + xx] : 0.f;
    }
    if (tid < 144) {
        int op = tid / 36, t = tid - op * 36;
        wp[op][t] = make_float2(w[(2 * op) * 36 + t], w[(2 * op + 1) * 36 + t]);
    }
    if (tid < 4) bpair[tid] = make_float2(b[2 * tid], b[2 * tid + 1]);
    __syncthreads();

    int op = tid >> 6, t64 = tid & 63;
    ull binit;
    PACK2(binit, bpair[op].x, bpair[op].y);
    #pragma unroll
    for (int i = 0; i < 4; i++) {
        int pos = t64 + i * 64;                 // 256 position-pairs
        int oy = pos >> 4, oxp = pos & 15;
        ull q[2][4];
        #pragma unroll
        for (int pr = 0; pr < 2; pr++)
            #pragma unroll
            for (int k = 0; k < 4; k++) q[pr][k] = binit;
        #pragma unroll
        for (int c = 0; c < 4; c++) {
            ull pb[4][6];
            #pragma unroll
            for (int rr = 0; rr < 4; rr++) {
                const float* base = &tile[c * C2_CH + (2 * oy + rr) * C2_STR + 4 * oxp];
                float4 a = *(const float4*)base;
                float2 b2 = *(const float2*)(base + 4);
                PACKB(pb[rr][0], a.x);  PACKB(pb[rr][1], a.y);
                PACKB(pb[rr][2], a.z);  PACKB(pb[rr][3], a.w);
                PACKB(pb[rr][4], b2.x); PACKB(pb[rr][5], b2.y);
            }
            #pragma unroll
            for (int dy = 0; dy < 3; dy++)
            #pragma unroll
            for (int dx = 0; dx < 3; dx++) {
                ull w2 = *(const ull*)&wp[op][c * 9 + dy * 3 + dx];
                FMA2(q[0][0], pb[dy    ][dx    ], w2);
                FMA2(q[0][1], pb[dy    ][dx + 1], w2);
                FMA2(q[0][2], pb[dy + 1][dx    ], w2);
                FMA2(q[0][3], pb[dy + 1][dx + 1], w2);
                FMA2(q[1][0], pb[dy    ][dx + 2], w2);
                FMA2(q[1][1], pb[dy    ][dx + 3], w2);
                FMA2(q[1][2], pb[dy + 1][dx + 2], w2);
                FMA2(q[1][3], pb[dy + 1][dx + 3], w2);
            }
        }
        // unpack, pool-max, relu, store (2 ocs x 2 cols)
        float m0e = -1e30f, m0o = -1e30f, m1e = -1e30f, m1o = -1e30f;
        #pragma unroll
        for (int k = 0; k < 4; k++) {
            float lo, hi;
            UNPK(lo, hi, q[0][k]); m0e = fmaxf(m0e, lo); m0o = fmaxf(m0o, hi);
            UNPK(lo, hi, q[1][k]); m1e = fmaxf(m1e, lo); m1o = fmaxf(m1o, hi);
        }
        int oc0 = 2 * op;
        float2 ve = make_float2(fmaxf(m0e, 0.f), fmaxf(m1e, 0.f));
        float2 vo = make_float2(fmaxf(m0o, 0.f), fmaxf(m1o, 0.f));
        *(float2*)&g_pool2[((n * 8 + oc0    ) * 32 + half * 16 + oy) * 32 + 2 * oxp] = ve;
        *(float2*)&g_pool2[((n * 8 + oc0 + 1) * 32 + half * 16 + oy) * 32 + 2 * oxp] = vo;
    }
}

// ---------------- FC as tiled GEMM with K-split ----------------
__global__ void __launch_bounds__(256) k_fc(const float* __restrict__ W) {
    int m0 = blockIdx.x * 32;
    int kb = blockIdx.y;
    int k0 = kb * KCHUNK;
    __shared__ float Xs[32][64];
    __shared__ float Ws[64][68];
    int tid = threadIdx.x;
    int tm = tid >> 5, tn = tid & 31;
    float acc[4][2] = {};
    for (int kt = 0; kt < KCHUNK; kt += 64) {
        #pragma unroll
        for (int i = 0; i < 8; i++) {
            int idx = tid + i * 256;
            int r = idx >> 6, c = idx & 63;
            int m = m0 + r;
            Xs[r][c] = (m < TOT_N) ? g_pool2[m * 8192 + k0 + kt + c] : 0.f;
        }
        #pragma unroll
        for (int i = 0; i < 16; i++) {
            int idx = tid + i * 256;
            int j = idx >> 6, c = idx & 63;
            Ws[j][c] = W[j * 8192 + k0 + kt + c];
        }
        __syncthreads();
        #pragma unroll
        for (int kk = 0; kk < 64; kk += 4) {
            float4 w0 = *(const float4*)&Ws[tn     ][kk];
            float4 w1 = *(const float4*)&Ws[tn + 32][kk];
            #pragma unroll
            for (int r = 0; r < 4; r++) {
                float4 xv = *(const float4*)&Xs[tm * 4 + r][kk];
                acc[r][0] += xv.x * w0.x + xv.y * w0.y + xv.z * w0.z + xv.w * w0.w;
                acc[r][1] += xv.x * w1.x + xv.y * w1.y + xv.z * w1.z + xv.w * w1.w;
            }
        }
        __syncthreads();
    }
    #pragma unroll
    for (int r = 0; r < 4; r++) {
        int m = m0 + tm * 4 + r;
        if (m < TOT_N) {
            g_fcp[(kb * TOT_N + m) * 64 + tn     ] = acc[r][0];
            g_fcp[(kb * TOT_N + m) * 64 + tn + 32] = acc[r][1];
        }
    }
}

// reduce K-split partials + bias -> g_item
__global__ void k_fcred(const float* __restrict__ b) {
    int idx = blockIdx.x * blockDim.x + threadIdx.x;
    if (idx >= TOT_N * 64) return;
    float s = b[idx & 63];
    #pragma unroll
    for (int kb = 0; kb < KSPLIT; kb++) s += g_fcp[kb * TOT_N * 64 + idx];
    g_item[idx] = s;
}

// ---------------- standardize per feature over a group (ddof=1) ----------------
__global__ void __launch_bounds__(1024) k_std() {
    int base = blockIdx.x ? CELL_N * 64 : 0;
    int N    = blockIdx.x ? DRUG_N : CELL_N;
    __shared__ float red[1024];
    __shared__ float mv[64];
    __shared__ float sv[64];
    float* x = g_item + base;
    int tid = threadIdx.x;
    int j = tid & 63, q = tid >> 6;
    float s = 0.f;
    for (int n = q; n < N; n += 16) s += x[n * 64 + j];
    red[tid] = s;
    __syncthreads();
    if (tid < 64) {
        float t = 0.f;
        #pragma unroll
        for (int k = 0; k < 16; k++) t += red[tid + 64 * k];
        mv[tid] = t / (float)N;
    }
    __syncthreads();
    float mean = mv[j];
    float ss = 0.f;
    for (int n = q; n < N; n += 16) { float d = x[n * 64 + j] - mean; ss += d * d; }
    __syncthreads();
    red[tid] = ss;
    __syncthreads();
    if (tid < 64) {
        float t = 0.f;
        #pragma unroll
        for (int k = 0; k < 16; k++) t += red[tid + 64 * k];
        sv[tid] = rsqrtf(t / (float)(N - 1));
    }
    __syncthreads();
    float inv = sv[j];
    for (int n = q; n < N; n += 16) x[n * 64 + j] = (x[n * 64 + j] - mean) * inv;
}

// ---------------- interact (merged cell+drug) ----------------
__global__ void k_interact(const int* __restrict__ cell_nbr, const int* __restrict__ drug_nbr,
                           const float* __restrict__ table) {
    int blk = blockIdx.x;
    const int* nbr;
    int nh, item_base, inter_base;
    if (blk < 2 * CELL_N) { nbr = cell_nbr; nh = blk; item_base = 0; inter_base = 0; }
    else { nbr = drug_nbr; nh = blk - 2 * CELL_N; item_base = CELL_N * 64; inter_base = CELL_N * 128; }
    int n = nh >> 1, h = nh & 1;
    __shared__ float rows[128 * 65];
    __shared__ float it[64];
    __shared__ int   idxs[128];
    __shared__ float sc[128];
    __shared__ float tmp[128];
    int tid = threadIdx.x;
    idxs[tid] = nbr[nh * 128 + tid];
    if (tid < 64) it[tid] = g_item[item_base + n * 64 + tid];
    __syncthreads();
    for (int e = tid; e < 128 * 64; e += 128) {
        int k = e >> 6, d = e & 63;
        rows[k * 65 + d] = table[idxs[k] * 64 + d];
    }
    __syncthreads();
    float s = 0.f;
    #pragma unroll 8
    for (int d = 0; d < 64; d++) s += rows[tid * 65 + d] * it[d];
    tmp[tid] = s;
    __syncthreads();
    #pragma unroll
    for (int off = 64; off; off >>= 1) {
        if (tid < off) tmp[tid] = fmaxf(tmp[tid], tmp[tid + off]);
        __syncthreads();
    }
    float mx = tmp[0];
    __syncthreads();
    float e = expf(s - mx);
    sc[tid] = e;
    tmp[tid] = e;
    __syncthreads();
    #pragma unroll
    for (int off = 64; off; off >>= 1) {
        if (tid < off) tmp[tid] += tmp[tid + off];
        __syncthreads();
    }
    float inv = 1.f / tmp[0];
    if (tid < 64) {
        float o = 0.f;
        #pragma unroll 8
        for (int k = 0; k < 128; k++) o += sc[k] * rows[k * 65 + tid];
        g_inter[inter_base + n * 128 + h * 64 + tid] = o * inv;
    }
}

// ---------------- agg + normsq + (cells) U ----------------
__global__ void k_agg(const float* __restrict__ W, const float* __restrict__ b,
                      const float* __restrict__ combw) {
    int n = blockIdx.x;
    __shared__ float xr[128];
    __shared__ float e[64];
    __shared__ float red[64];
    int tid = threadIdx.x;
    xr[tid] = g_inter[n * 128 + tid];
    __syncthreads();
    if (tid < 64) {
        float s = b[tid];
        #pragma unroll 8
        for (int t = 0; t < 128; t++) s += W[tid * 128 + t] * xr[t];
        g_emb[n * 64 + tid] = s;
        e[tid] = s;
        red[tid] = s * s;
    }
    __syncthreads();
    if (tid < 32) {
        float v = red[tid] + red[tid + 32];
        #pragma unroll
        for (int o = 16; o; o >>= 1) v += __shfl_down_sync(0xffffffffu, v, o);
        if (tid == 0) g_normsq[n] = v;
    }
    if (n < CELL_N) {
        float s = 0.f;
        #pragma unroll 8
        for (int j = 0; j < 64; j++) s += combw[j * 128 + tid] * e[j];
        g_U[n * 128 + tid] = s;
    }
}

// ---------------- per-batch score + item_reg partials ----------------
__global__ void k_score(const int* __restrict__ data, float* __restrict__ out) {
    int bidx = blockIdx.x * blockDim.x + threadIdx.x;
    float reg = 0.f;
    if (bidx < BATCH) {
        int c  = data[3 * bidx];
        int d1 = data[3 * bidx + 1];
        int d2 = data[3 * bidx + 2];
        const float* e1 = g_emb + (CELL_N + d1) * 64;
        const float* e2 = g_emb + (CELL_N + d2) * 64;
        const float* u  = g_U + c * 128;
        float s = 0.f;
        #pragma unroll 8
        for (int t = 0; t < 64; t++) {
            float a = e1[t], bb = e2[t];
            s += a * u[t] + bb * u[64 + t] - a * bb;
        }
        out[bidx] = s;
        reg = 0.5f * (g_normsq[c] + g_normsq[CELL_N + d1] + g_normsq[CELL_N + d2]);
    }
    __shared__ float red[128];
    red[threadIdx.x] = reg;
    __syncthreads();
    #pragma unroll
    for (int off = 64; off; off >>= 1) {
        if (threadIdx.x < off) red[threadIdx.x] += red[threadIdx.x + off];
        __syncthreads();
    }
    if (threadIdx.x == 0) g_part[blockIdx.x] = red[0];
}

// ---------------- node_reg + loss ----------------
__global__ void k_loss(const int* __restrict__ data, const int* __restrict__ cell_nbr,
                       const int* __restrict__ drug_nbr, float* __restrict__ out, int loss_idx) {
    __shared__ float red[256];
    int tid = threadIdx.x;
    float s = 0.f;
    for (int e = tid; e < 1536; e += 256) {
        int set = e >> 8, off = e & 255;
        int hop = set / 3, which = set - hop * 3;
        int nodeidx = data[hop * 3 + which];
        int p = (which == 0) ? cell_nbr[nodeidx * 256 + off] : drug_nbr[nodeidx * 256 + off];
        s += g_tablesq[p];
    }
    red[tid] = s;
    __syncthreads();
    #pragma unroll
    for (int off = 128; off; off >>= 1) {
        if (tid < off) red[tid] += red[tid + off];
        __syncthreads();
    }
    if (tid == 0) {
        float item_reg = 0.f;
        #pragma unroll
        for (int i = 0; i < 32; i++) item_reg += g_part[i];
        out[loss_idx] = 1e-6f * (item_reg + 0.5f * red[0]) / (float)BATCH;
    }
}

// ---------------- launch ----------------
extern "C" void kernel_launch(void* const* d_in, const int* in_sizes, int n_in,
                              void* d_out, int out_size) {
    const int*   data     = (const int*)  d_in[0];
    const int*   cell_nbr = (const int*)  d_in[1];
    const int*   drug_nbr = (const int*)  d_in[2];
    const float* table    = (const float*)d_in[3];
    const float* cell_pre = (const float*)d_in[4];
    const float* drug_pre = (const float*)d_in[5];
    const float* c1w      = (const float*)d_in[6];
    const float* c1b      = (const float*)d_in[7];
    const float* c2w      = (const float*)d_in[8];
    const float* c2b      = (const float*)d_in[9];
    const float* ow       = (const float*)d_in[10];
    const float* ob       = (const float*)d_in[11];
    const float* aw       = (const float*)d_in[12];
    const float* ab       = (const float*)d_in[13];
    const float* cw       = (const float*)d_in[14];
    float* out = (float*)d_out;

    k_tablesq<<<(NPROT * 32 + 255) / 256, 256>>>(table);

    k_conv1<<<CELL_N * 2, 256>>>(cell_pre, c1w, c1b, 0);
    k_conv1<<<DRUG_N * 2, 256>>>(drug_pre, c1w, c1b, CELL_N * 4 * 64 * 64);
    k_conv2<<<TOT_N * 2, 256>>>(c2w, c2b);

    dim3 fcg(27, KSPLIT);
    k_fc<<<fcg, 256>>>(ow);
    k_fcred<<<(TOT_N * 64 + 255) / 256, 256>>>(ob);

    k_std<<<2, 1024>>>();

    k_interact<<<TOT_N * 2, 128>>>(cell_nbr, drug_nbr, table);

    k_agg<<<TOT_N, 128>>>(aw, ab, cw);
    k_score<<<32, 128>>>(data, out);
    k_loss<<<1, 256>>>(data, cell_nbr, drug_nbr, out, out_size - 1);
}

// round 5
// speedup vs baseline: 1.1366x; 1.0008x over previous
#include <cuda_runtime.h>

#define CELL_N 76
#define DRUG_N 764
#define TOT_N  840
#define BATCH  4096
#define NPROT  15970
#define KSPLIT 8
#define KCHUNK 1024  // 8192 / KSPLIT

// ---------------- scratch (device globals; no allocs allowed) ----------------
__device__ float g_pool1[TOT_N * 4 * 64 * 64];
__device__ float g_pool2[TOT_N * 8 * 32 * 32];
__device__ float g_fcp  [KSPLIT * TOT_N * 64];
__device__ float g_item [TOT_N * 64];
__device__ float g_inter[TOT_N * 128];
__device__ float g_emb  [TOT_N * 64];
__device__ float g_normsq[TOT_N];
__device__ float g_U    [CELL_N * 128];
__device__ float g_tablesq[NPROT];

// ---------------- conv1 (merged cell+drug) + tablesq side-blocks ----------------
// blocks [0, 1680): conv1 on image (gn, half); blocks [1680, 1680+1997): tablesq
#define TSQ_BLK0 (TOT_N * 2)
__global__ void __launch_bounds__(256) k_conv1(
        const float* __restrict__ cell_pre, const float* __restrict__ drug_pre,
        const float* __restrict__ w, const float* __restrict__ b,
        const float* __restrict__ table) {
    int blk = blockIdx.x;
    int tid = threadIdx.x;
    if (blk >= TSQ_BLK0) {
        // tablesq: 8 proteins per block (one per warp)
        int warp = (blk - TSQ_BLK0) * 8 + (tid >> 5);
        int lane = tid & 31;
        if (warp >= NPROT) return;
        const float* r = table + warp * 64;
        float a = r[lane], bb = r[lane + 32];
        float s = a * a + bb * bb;
        #pragma unroll
        for (int o = 16; o; o >>= 1) s += __shfl_down_sync(0xffffffffu, s, o);
        if (lane == 0) g_tablesq[warp] = s;
        return;
    }
    int half = blk & 1;
    int gn;
    const float* x;
    if (blk < 2 * CELL_N) { gn = blk >> 1; x = cell_pre + gn * 16384; }
    else { int n = (blk - 2 * CELL_N) >> 1; gn = CELL_N + n; x = drug_pre + n * 16384; }
    __shared__ float tile[66 * 130];
    float wr[36];
    #pragma unroll
    for (int i = 0; i < 36; i++) wr[i] = w[i];
    float bb[4] = { b[0], b[1], b[2], b[3] };
    int row0 = half * 64 - 1;
    for (int idx = tid; idx < 66 * 130; idx += 256) {
        int r = idx / 130, c = idx - r * 130;
        int y = row0 + r, xx = c - 1;
        tile[idx] = (y >= 0 && y < 128 && (unsigned)xx < 128u) ? x[y * 128 + xx] : 0.f;
    }
    __syncthreads();
    #pragma unroll
    for (int i = 0; i < 8; i++) {
        int pos = tid + i * 256;
        int oy = pos >> 6, ox = pos & 63;
        float p[4][4];
        #pragma unroll
        for (int r = 0; r < 4; r++) {
            const float2* s = (const float2*)&tile[(2 * oy + r) * 130 + 2 * ox];
            float2 a = s[0], d = s[1];
            p[r][0] = a.x; p[r][1] = a.y; p[r][2] = d.x; p[r][3] = d.y;
        }
        #pragma unroll
        for (int oc = 0; oc < 4; oc++) {
            float q00 = bb[oc], q01 = bb[oc], q10 = bb[oc], q11 = bb[oc];
            #pragma unroll
            for (int dy = 0; dy < 3; dy++)
            #pragma unroll
            for (int dx = 0; dx < 3; dx++) {
                float wv = wr[oc * 9 + dy * 3 + dx];
                q00 += p[dy    ][dx    ] * wv;
                q01 += p[dy    ][dx + 1] * wv;
                q10 += p[dy + 1][dx    ] * wv;
                q11 += p[dy + 1][dx + 1] * wv;
            }
            float m = fmaxf(fmaxf(q00, q01), fmaxf(q10, q11));
            g_pool1[((gn * 4 + oc) * 64 + half * 32 + oy) * 64 + ox] = fmaxf(m, 0.f);
        }
    }
}

// ---------------- conv2 (4->8) + relu + pool, scalar pair-output blocking ----------------
// grid = TOT_N*2, block = 256. oc = tid>>5 per warp; 8 iterations of output-pairs.
#define C2_STR 68
#define C2_CH  (34 * C2_STR)
__global__ void __launch_bounds__(256, 3) k_conv2(
        const float* __restrict__ w, const float* __restrict__ b) {
    int n = blockIdx.x >> 1, half = blockIdx.x & 1;
    __shared__ float tile[4 * C2_CH];
    int tid = threadIdx.x;
    int row0 = half * 32 - 1;
    for (int idx = tid; idx < 4 * 34 * 66; idx += 256) {
        int c = idx / (34 * 66), rem = idx - c * (34 * 66);
        int r = rem / 66, cc = rem - r * 66;
        int y = row0 + r, xx = cc - 1;
        tile[c * C2_CH + r * C2_STR + cc] =
            ((unsigned)y < 64u && (unsigned)xx < 64u)
          ? g_pool1[((n * 4 + c) * 64 + y) * 64 + xx] : 0.f;
    }
    __syncthreads();
    int oc = tid >> 5, lane = tid & 31;
    float wr[36];
    #pragma unroll
    for (int i = 0; i < 36; i++) wr[i] = w[oc * 36 + i];
    float bs = b[oc];
    #pragma unroll
    for (int i = 0; i < 8; i++) {
        int pos = lane + i * 32;                // 256 output-pairs per oc
        int oy = pos >> 4, oxp = pos & 15;
        float q[8];
        #pragma unroll
        for (int k = 0; k < 8; k++) q[k] = bs;
        #pragma unroll
        for (int c = 0; c < 4; c++) {
            float pt[4][6];
            #pragma unroll
            for (int rr = 0; rr < 4; rr++) {
                const float* base = &tile[c * C2_CH + (2 * oy + rr) * C2_STR + 4 * oxp];
                float4 a = *(const float4*)base;
                float2 b2 = *(const float2*)(base + 4);
                pt[rr][0] = a.x; pt[rr][1] = a.y; pt[rr][2] = a.z;
                pt[rr][3] = a.w; pt[rr][4] = b2.x; pt[rr][5] = b2.y;
            }
            #pragma unroll
            for (int dy = 0; dy < 3; dy++)
            #pragma unroll
            for (int dx = 0; dx < 3; dx++) {
                float wv = wr[c * 9 + dy * 3 + dx];
                q[0] += pt[dy    ][dx    ] * wv;
                q[1] += pt[dy    ][dx + 1] * wv;
                q[2] += pt[dy + 1][dx    ] * wv;
                q[3] += pt[dy + 1][dx + 1] * wv;
                q[4] += pt[dy    ][dx + 2] * wv;
                q[5] += pt[dy    ][dx + 3] * wv;
                q[6] += pt[dy + 1][dx + 2] * wv;
                q[7] += pt[dy + 1][dx + 3] * wv;
            }
        }
        float m0 = fmaxf(fmaxf(q[0], q[1]), fmaxf(q[2], q[3]));
        float m1 = fmaxf(fmaxf(q[4], q[5]), fmaxf(q[6], q[7]));
        float2 v = make_float2(fmaxf(m0, 0.f), fmaxf(m1, 0.f));
        *(float2*)&g_pool2[((n * 8 + oc) * 32 + half * 16 + oy) * 32 + 2 * oxp] = v;
    }
}

// ---------------- FC as tiled GEMM with K-split ----------------
__global__ void __launch_bounds__(256) k_fc(const float* __restrict__ W) {
    int m0 = blockIdx.x * 32;
    int kb = blockIdx.y;
    int k0 = kb * KCHUNK;
    __shared__ float Xs[32][64];
    __shared__ float Ws[64][68];
    int tid = threadIdx.x;
    int tm = tid >> 5, tn = tid & 31;
    float acc[4][2] = {};
    for (int kt = 0; kt < KCHUNK; kt += 64) {
        #pragma unroll
        for (int i = 0; i < 8; i++) {
            int idx = tid + i * 256;
            int r = idx >> 6, c = idx & 63;
            int m = m0 + r;
            Xs[r][c] = (m < TOT_N) ? g_pool2[m * 8192 + k0 + kt + c] : 0.f;
        }
        #pragma unroll
        for (int i = 0; i < 16; i++) {
            int idx = tid + i * 256;
            int j = idx >> 6, c = idx & 63;
            Ws[j][c] = W[j * 8192 + k0 + kt + c];
        }
        __syncthreads();
        #pragma unroll
        for (int kk = 0; kk < 64; kk += 4) {
            float4 w0 = *(const float4*)&Ws[tn     ][kk];
            float4 w1 = *(const float4*)&Ws[tn + 32][kk];
            #pragma unroll
            for (int r = 0; r < 4; r++) {
                float4 xv = *(const float4*)&Xs[tm * 4 + r][kk];
                acc[r][0] += xv.x * w0.x + xv.y * w0.y + xv.z * w0.z + xv.w * w0.w;
                acc[r][1] += xv.x * w1.x + xv.y * w1.y + xv.z * w1.z + xv.w * w1.w;
            }
        }
        __syncthreads();
    }
    #pragma unroll
    for (int r = 0; r < 4; r++) {
        int m = m0 + tm * 4 + r;
        if (m < TOT_N) {
            g_fcp[(kb * TOT_N + m) * 64 + tn     ] = acc[r][0];
            g_fcp[(kb * TOT_N + m) * 64 + tn + 32] = acc[r][1];
        }
    }
}

// ---------------- fcred + standardize fused ----------------
// grid = 2 (cells, drugs), block = 1024. Pass 1 sums K-split partials + bias,
// writes g_item and accumulates mean; pass 2 variance; pass 3 normalize.
__global__ void __launch_bounds__(1024) k_std(const float* __restrict__ ob) {
    int row0 = blockIdx.x ? CELL_N : 0;
    int N    = blockIdx.x ? DRUG_N : CELL_N;
    __shared__ float red[1024];
    __shared__ float mv[64];
    __shared__ float sv[64];
    int tid = threadIdx.x;
    int j = tid & 63, q = tid >> 6;
    float bj = ob[j];
    float s = 0.f;
    for (int n = q; n < N; n += 16) {
        int row = row0 + n;
        float v = bj;
        #pragma unroll
        for (int kb = 0; kb < KSPLIT; kb++) v += g_fcp[(kb * TOT_N + row) * 64 + j];
        g_item[row * 64 + j] = v;
        s += v;
    }
    red[tid] = s;
    __syncthreads();
    if (tid < 64) {
        float t = 0.f;
        #pragma unroll
        for (int k = 0; k < 16; k++) t += red[tid + 64 * k];
        mv[tid] = t / (float)N;
    }
    __syncthreads();
    float mean = mv[j];
    float ss = 0.f;
    for (int n = q; n < N; n += 16) {
        float d = g_item[(row0 + n) * 64 + j] - mean;
        ss += d * d;
    }
    __syncthreads();
    red[tid] = ss;
    __syncthreads();
    if (tid < 64) {
        float t = 0.f;
        #pragma unroll
        for (int k = 0; k < 16; k++) t += red[tid + 64 * k];
        sv[tid] = rsqrtf(t / (float)(N - 1));
    }
    __syncthreads();
    float inv = sv[j];
    for (int n = q; n < N; n += 16) {
        int row = row0 + n;
        g_item[row * 64 + j] = (g_item[row * 64 + j] - mean) * inv;
    }
}

// ---------------- interact (merged cell+drug) ----------------
__global__ void k_interact(const int* __restrict__ cell_nbr, const int* __restrict__ drug_nbr,
                           const float* __restrict__ table) {
    int blk = blockIdx.x;
    const int* nbr;
    int nh, item_base, inter_base;
    if (blk < 2 * CELL_N) { nbr = cell_nbr; nh = blk; item_base = 0; inter_base = 0; }
    else { nbr = drug_nbr; nh = blk - 2 * CELL_N; item_base = CELL_N * 64; inter_base = CELL_N * 128; }
    int n = nh >> 1, h = nh & 1;
    __shared__ float rows[128 * 65];
    __shared__ float it[64];
    __shared__ int   idxs[128];
    __shared__ float sc[128];
    __shared__ float tmp[128];
    int tid = threadIdx.x;
    idxs[tid] = nbr[nh * 128 + tid];
    if (tid < 64) it[tid] = g_item[item_base + n * 64 + tid];
    __syncthreads();
    for (int e = tid; e < 128 * 64; e += 128) {
        int k = e >> 6, d = e & 63;
        rows[k * 65 + d] = table[idxs[k] * 64 + d];
    }
    __syncthreads();
    float s = 0.f;
    #pragma unroll 8
    for (int d = 0; d < 64; d++) s += rows[tid * 65 + d] * it[d];
    tmp[tid] = s;
    __syncthreads();
    #pragma unroll
    for (int off = 64; off; off >>= 1) {
        if (tid < off) tmp[tid] = fmaxf(tmp[tid], tmp[tid + off]);
        __syncthreads();
    }
    float mx = tmp[0];
    __syncthreads();
    float e = expf(s - mx);
    sc[tid] = e;
    tmp[tid] = e;
    __syncthreads();
    #pragma unroll
    for (int off = 64; off; off >>= 1) {
        if (tid < off) tmp[tid] += tmp[tid + off];
        __syncthreads();
    }
    float inv = 1.f / tmp[0];
    if (tid < 64) {
        float o = 0.f;
        #pragma unroll 8
        for (int k = 0; k < 128; k++) o += sc[k] * rows[k * 65 + tid];
        g_inter[inter_base + n * 128 + h * 64 + tid] = o * inv;
    }
}

// ---------------- agg + normsq + (cells) U ----------------
__global__ void k_agg(const float* __restrict__ W, const float* __restrict__ b,
                      const float* __restrict__ combw) {
    int n = blockIdx.x;
    __shared__ float xr[128];
    __shared__ float e[64];
    __shared__ float red[64];
    int tid = threadIdx.x;
    xr[tid] = g_inter[n * 128 + tid];
    __syncthreads();
    if (tid < 64) {
        float s = b[tid];
        #pragma unroll 8
        for (int t = 0; t < 128; t++) s += W[tid * 128 + t] * xr[t];
        g_emb[n * 64 + tid] = s;
        e[tid] = s;
        red[tid] = s * s;
    }
    __syncthreads();
    if (tid < 32) {
        float v = red[tid] + red[tid + 32];
        #pragma unroll
        for (int o = 16; o; o >>= 1) v += __shfl_down_sync(0xffffffffu, v, o);
        if (tid == 0) g_normsq[n] = v;
    }
    if (n < CELL_N) {
        float s = 0.f;
        #pragma unroll 8
        for (int j = 0; j < 64; j++) s += combw[j * 128 + tid] * e[j];
        g_U[n * 128 + tid] = s;
    }
}

// ---------------- score (blocks 0..15) + loss (block 16), one launch ----------------
__global__ void __launch_bounds__(256) k_scoreloss(
        const int* __restrict__ data, const int* __restrict__ cell_nbr,
        const int* __restrict__ drug_nbr, float* __restrict__ out, int loss_idx) {
    int blk = blockIdx.x;
    int tid = threadIdx.x;
    if (blk < 16) {
        int bidx = blk * 256 + tid;
        int c  = data[3 * bidx];
        int d1 = data[3 * bidx + 1];
        int d2 = data[3 * bidx + 2];
        const float* e1 = g_emb + (CELL_N + d1) * 64;
        const float* e2 = g_emb + (CELL_N + d2) * 64;
        const float* u  = g_U + c * 128;
        float s = 0.f;
        #pragma unroll 8
        for (int t = 0; t < 64; t++) {
            float a = e1[t], bb = e2[t];
            s += a * u[t] + bb * u[64 + t] - a * bb;
        }
        out[bidx] = s;
        return;
    }
    // loss block: item_reg over all 4096 triples (normsq cached in smem) + node_reg
    __shared__ float nsq[TOT_N];
    __shared__ float red[256];
    for (int i = tid; i < TOT_N; i += 256) nsq[i] = g_normsq[i];
    __syncthreads();
    float ir = 0.f;
    for (int bidx = tid; bidx < BATCH; bidx += 256) {
        int c  = data[3 * bidx];
        int d1 = data[3 * bidx + 1];
        int d2 = data[3 * bidx + 2];
        ir += nsq[c] + nsq[CELL_N + d1] + nsq[CELL_N + d2];
    }
    float nr = 0.f;
    for (int e = tid; e < 1536; e += 256) {
        int set = e >> 8, off = e & 255;
        int hop = set / 3, which = set - hop * 3;
        int nodeidx = data[hop * 3 + which];
        int p = (which == 0) ? cell_nbr[nodeidx * 256 + off] : drug_nbr[nodeidx * 256 + off];
        nr += g_tablesq[p];
    }
    red[tid] = 0.5f * ir + 0.5f * nr;
    __syncthreads();
    #pragma unroll
    for (int off = 128; off; off >>= 1) {
        if (tid < off) red[tid] += red[tid + off];
        __syncthreads();
    }
    if (tid == 0) out[loss_idx] = 1e-6f * red[0] / (float)BATCH;
}

// ---------------- launch ----------------
extern "C" void kernel_launch(void* const* d_in, const int* in_sizes, int n_in,
                              void* d_out, int out_size) {
    const int*   data     = (const int*)  d_in[0];
    const int*   cell_nbr = (const int*)  d_in[1];
    const int*   drug_nbr = (const int*)  d_in[2];
    const float* table    = (const float*)d_in[3];
    const float* cell_pre = (const float*)d_in[4];
    const float* drug_pre = (const float*)d_in[5];
    const float* c1w      = (const float*)d_in[6];
    const float* c1b      = (const float*)d_in[7];
    const float* c2w      = (const float*)d_in[8];
    const float* c2b      = (const float*)d_in[9];
    const float* ow       = (const float*)d_in[10];
    const float* ob       = (const float*)d_in[11];
    const float* aw       = (const float*)d_in[12];
    const float* ab       = (const float*)d_in[13];
    const float* cw       = (const float*)d_in[14];
    float* out = (float*)d_out;

    int tsq_blocks = (NPROT + 7) / 8;
    k_conv1<<<TSQ_BLK0 + tsq_blocks, 256>>>(cell_pre, drug_pre, c1w, c1b, table);
    k_conv2<<<TOT_N * 2, 256>>>(c2w, c2b);

    dim3 fcg(27, KSPLIT);
    k_fc<<<fcg, 256>>>(ow);
    k_std<<<2, 1024>>>(ob);

    k_interact<<<TOT_N * 2, 128>>>(cell_nbr, drug_nbr, table);
    k_agg<<<TOT_N, 128>>>(aw, ab, cw);
    k_scoreloss<<<17, 256>>>(data, cell_nbr, drug_nbr, out, out_size - 1);
}

// round 6
// speedup vs baseline: 1.1598x; 1.0205x over previous
#include <cuda_runtime.h>

#define CELL_N 76
#define DRUG_N 764
#define TOT_N  840
#define BATCH  4096
#define NPROT  15970
#define KSPLIT 8
#define KCHUNK 1024  // 8192 / KSPLIT

// ---------------- scratch (device globals; no allocs allowed) ----------------
__device__ float g_pool1[TOT_N * 4 * 64 * 64];
__device__ float g_pool2[TOT_N * 8 * 32 * 32];
__device__ float g_fcp  [KSPLIT * TOT_N * 64];
__device__ float g_item [TOT_N * 64];
__device__ float g_inter[TOT_N * 128];
__device__ float g_emb  [TOT_N * 64];
__device__ float g_normsq[TOT_N];
__device__ float g_U    [CELL_N * 128];
__device__ float g_tablesq[NPROT];

// ---------------- conv1 (merged cell+drug) + tablesq side-blocks ----------------
#define TSQ_BLK0 (TOT_N * 2)
__global__ void __launch_bounds__(256) k_conv1(
        const float* __restrict__ cell_pre, const float* __restrict__ drug_pre,
        const float* __restrict__ w, const float* __restrict__ b,
        const float* __restrict__ table) {
    int blk = blockIdx.x;
    int tid = threadIdx.x;
    if (blk >= TSQ_BLK0) {
        int warp = (blk - TSQ_BLK0) * 8 + (tid >> 5);
        int lane = tid & 31;
        if (warp >= NPROT) return;
        const float* r = table + warp * 64;
        float a = r[lane], bb = r[lane + 32];
        float s = a * a + bb * bb;
        #pragma unroll
        for (int o = 16; o; o >>= 1) s += __shfl_down_sync(0xffffffffu, s, o);
        if (lane == 0) g_tablesq[warp] = s;
        return;
    }
    int half = blk & 1;
    int gn;
    const float* x;
    if (blk < 2 * CELL_N) { gn = blk >> 1; x = cell_pre + gn * 16384; }
    else { int n = (blk - 2 * CELL_N) >> 1; gn = CELL_N + n; x = drug_pre + n * 16384; }
    __shared__ float tile[66 * 130];
    float wr[36];
    #pragma unroll
    for (int i = 0; i < 36; i++) wr[i] = w[i];
    float bb[4] = { b[0], b[1], b[2], b[3] };
    int row0 = half * 64 - 1;
    for (int idx = tid; idx < 66 * 130; idx += 256) {
        int r = idx / 130, c = idx - r * 130;
        int y = row0 + r, xx = c - 1;
        tile[idx] = (y >= 0 && y < 128 && (unsigned)xx < 128u) ? x[y * 128 + xx] : 0.f;
    }
    __syncthreads();
    #pragma unroll
    for (int i = 0; i < 8; i++) {
        int pos = tid + i * 256;
        int oy = pos >> 6, ox = pos & 63;
        float p[4][4];
        #pragma unroll
        for (int r = 0; r < 4; r++) {
            const float2* s = (const float2*)&tile[(2 * oy + r) * 130 + 2 * ox];
            float2 a = s[0], d = s[1];
            p[r][0] = a.x; p[r][1] = a.y; p[r][2] = d.x; p[r][3] = d.y;
        }
        #pragma unroll
        for (int oc = 0; oc < 4; oc++) {
            float q00 = bb[oc], q01 = bb[oc], q10 = bb[oc], q11 = bb[oc];
            #pragma unroll
            for (int dy = 0; dy < 3; dy++)
            #pragma unroll
            for (int dx = 0; dx < 3; dx++) {
                float wv = wr[oc * 9 + dy * 3 + dx];
                q00 += p[dy    ][dx    ] * wv;
                q01 += p[dy    ][dx + 1] * wv;
                q10 += p[dy + 1][dx    ] * wv;
                q11 += p[dy + 1][dx + 1] * wv;
            }
            float m = fmaxf(fmaxf(q00, q01), fmaxf(q10, q11));
            g_pool1[((gn * 4 + oc) * 64 + half * 32 + oy) * 64 + ox] = fmaxf(m, 0.f);
        }
    }
}

// ---------------- conv2 (4->8) + relu + pool, scalar pair-output blocking ----------------
#define C2_STR 68
#define C2_CH  (34 * C2_STR)
__global__ void __launch_bounds__(256, 3) k_conv2(
        const float* __restrict__ w, const float* __restrict__ b) {
    int n = blockIdx.x >> 1, half = blockIdx.x & 1;
    __shared__ float tile[4 * C2_CH];
    int tid = threadIdx.x;
    int row0 = half * 32 - 1;
    for (int idx = tid; idx < 4 * 34 * 66; idx += 256) {
        int c = idx / (34 * 66), rem = idx - c * (34 * 66);
        int r = rem / 66, cc = rem - r * 66;
        int y = row0 + r, xx = cc - 1;
        tile[c * C2_CH + r * C2_STR + cc] =
            ((unsigned)y < 64u && (unsigned)xx < 64u)
          ? g_pool1[((n * 4 + c) * 64 + y) * 64 + xx] : 0.f;
    }
    __syncthreads();
    int oc = tid >> 5, lane = tid & 31;
    float wr[36];
    #pragma unroll
    for (int i = 0; i < 36; i++) wr[i] = w[oc * 36 + i];
    float bs = b[oc];
    #pragma unroll
    for (int i = 0; i < 8; i++) {
        int pos = lane + i * 32;
        int oy = pos >> 4, oxp = pos & 15;
        float q[8];
        #pragma unroll
        for (int k = 0; k < 8; k++) q[k] = bs;
        #pragma unroll
        for (int c = 0; c < 4; c++) {
            float pt[4][6];
            #pragma unroll
            for (int rr = 0; rr < 4; rr++) {
                const float* base = &tile[c * C2_CH + (2 * oy + rr) * C2_STR + 4 * oxp];
                float4 a = *(const float4*)base;
                float2 b2 = *(const float2*)(base + 4);
                pt[rr][0] = a.x; pt[rr][1] = a.y; pt[rr][2] = a.z;
                pt[rr][3] = a.w; pt[rr][4] = b2.x; pt[rr][5] = b2.y;
            }
            #pragma unroll
            for (int dy = 0; dy < 3; dy++)
            #pragma unroll
            for (int dx = 0; dx < 3; dx++) {
                float wv = wr[c * 9 + dy * 3 + dx];
                q[0] += pt[dy    ][dx    ] * wv;
                q[1] += pt[dy    ][dx + 1] * wv;
                q[2] += pt[dy + 1][dx    ] * wv;
                q[3] += pt[dy + 1][dx + 1] * wv;
                q[4] += pt[dy    ][dx + 2] * wv;
                q[5] += pt[dy    ][dx + 3] * wv;
                q[6] += pt[dy + 1][dx + 2] * wv;
                q[7] += pt[dy + 1][dx + 3] * wv;
            }
        }
        float m0 = fmaxf(fmaxf(q[0], q[1]), fmaxf(q[2], q[3]));
        float m1 = fmaxf(fmaxf(q[4], q[5]), fmaxf(q[6], q[7]));
        float2 v = make_float2(fmaxf(m0, 0.f), fmaxf(m1, 0.f));
        *(float2*)&g_pool2[((n * 8 + oc) * 32 + half * 16 + oy) * 32 + 2 * oxp] = v;
    }
}

// ---------------- FC as tiled GEMM with K-split ----------------
__global__ void __launch_bounds__(256) k_fc(const float* __restrict__ W) {
    int m0 = blockIdx.x * 32;
    int kb = blockIdx.y;
    int k0 = kb * KCHUNK;
    __shared__ float Xs[32][64];
    __shared__ float Ws[64][68];
    int tid = threadIdx.x;
    int tm = tid >> 5, tn = tid & 31;
    float acc[4][2] = {};
    for (int kt = 0; kt < KCHUNK; kt += 64) {
        #pragma unroll
        for (int i = 0; i < 8; i++) {
            int idx = tid + i * 256;
            int r = idx >> 6, c = idx & 63;
            int m = m0 + r;
            Xs[r][c] = (m < TOT_N) ? g_pool2[m * 8192 + k0 + kt + c] : 0.f;
        }
        #pragma unroll
        for (int i = 0; i < 16; i++) {
            int idx = tid + i * 256;
            int j = idx >> 6, c = idx & 63;
            Ws[j][c] = W[j * 8192 + k0 + kt + c];
        }
        __syncthreads();
        #pragma unroll
        for (int kk = 0; kk < 64; kk += 4) {
            float4 w0 = *(const float4*)&Ws[tn     ][kk];
            float4 w1 = *(const float4*)&Ws[tn + 32][kk];
            #pragma unroll
            for (int r = 0; r < 4; r++) {
                float4 xv = *(const float4*)&Xs[tm * 4 + r][kk];
                acc[r][0] += xv.x * w0.x + xv.y * w0.y + xv.z * w0.z + xv.w * w0.w;
                acc[r][1] += xv.x * w1.x + xv.y * w1.y + xv.z * w1.z + xv.w * w1.w;
            }
        }
        __syncthreads();
    }
    #pragma unroll
    for (int r = 0; r < 4; r++) {
        int m = m0 + tm * 4 + r;
        if (m < TOT_N) {
            g_fcp[(kb * TOT_N + m) * 64 + tn     ] = acc[r][0];
            g_fcp[(kb * TOT_N + m) * 64 + tn + 32] = acc[r][1];
        }
    }
}

// ---------------- reduce K-split partials + bias -> g_item (wide grid) ----------------
__global__ void k_fcred(const float* __restrict__ b) {
    int idx = blockIdx.x * blockDim.x + threadIdx.x;
    if (idx >= TOT_N * 64) return;
    float s = b[idx & 63];
    #pragma unroll
    for (int kb = 0; kb < KSPLIT; kb++) s += g_fcp[kb * TOT_N * 64 + idx];
    g_item[idx] = s;
}

// ---------------- standardize per feature over a group (ddof=1), reads g_item only ----------------
__global__ void __launch_bounds__(1024) k_std() {
    int row0 = blockIdx.x ? CELL_N : 0;
    int N    = blockIdx.x ? DRUG_N : CELL_N;
    __shared__ float red[1024];
    __shared__ float mv[64];
    __shared__ float sv[64];
    int tid = threadIdx.x;
    int j = tid & 63, q = tid >> 6;
    float s = 0.f;
    for (int n = q; n < N; n += 16) s += g_item[(row0 + n) * 64 + j];
    red[tid] = s;
    __syncthreads();
    if (tid < 64) {
        float t = 0.f;
        #pragma unroll
        for (int k = 0; k < 16; k++) t += red[tid + 64 * k];
        mv[tid] = t / (float)N;
    }
    __syncthreads();
    float mean = mv[j];
    float ss = 0.f;
    for (int n = q; n < N; n += 16) {
        float d = g_item[(row0 + n) * 64 + j] - mean;
        ss += d * d;
    }
    __syncthreads();
    red[tid] = ss;
    __syncthreads();
    if (tid < 64) {
        float t = 0.f;
        #pragma unroll
        for (int k = 0; k < 16; k++) t += red[tid + 64 * k];
        sv[tid] = rsqrtf(t / (float)(N - 1));
    }
    __syncthreads();
    float inv = sv[j];
    for (int n = q; n < N; n += 16) {
        int row = row0 + n;
        g_item[row * 64 + j] = (g_item[row * 64 + j] - mean) * inv;
    }
}

// ---------------- interact (merged cell+drug) ----------------
__global__ void k_interact(const int* __restrict__ cell_nbr, const int* __restrict__ drug_nbr,
                           const float* __restrict__ table) {
    int blk = blockIdx.x;
    const int* nbr;
    int nh, item_base, inter_base;
    if (blk < 2 * CELL_N) { nbr = cell_nbr; nh = blk; item_base = 0; inter_base = 0; }
    else { nbr = drug_nbr; nh = blk - 2 * CELL_N; item_base = CELL_N * 64; inter_base = CELL_N * 128; }
    int n = nh >> 1, h = nh & 1;
    __shared__ float rows[128 * 65];
    __shared__ float it[64];
    __shared__ int   idxs[128];
    __shared__ float sc[128];
    __shared__ float tmp[128];
    int tid = threadIdx.x;
    idxs[tid] = nbr[nh * 128 + tid];
    if (tid < 64) it[tid] = g_item[item_base + n * 64 + tid];
    __syncthreads();
    for (int e = tid; e < 128 * 64; e += 128) {
        int k = e >> 6, d = e & 63;
        rows[k * 65 + d] = table[idxs[k] * 64 + d];
    }
    __syncthreads();
    float s = 0.f;
    #pragma unroll 8
    for (int d = 0; d < 64; d++) s += rows[tid * 65 + d] * it[d];
    tmp[tid] = s;
    __syncthreads();
    #pragma unroll
    for (int off = 64; off; off >>= 1) {
        if (tid < off) tmp[tid] = fmaxf(tmp[tid], tmp[tid + off]);
        __syncthreads();
    }
    float mx = tmp[0];
    __syncthreads();
    float e = expf(s - mx);
    sc[tid] = e;
    tmp[tid] = e;
    __syncthreads();
    #pragma unroll
    for (int off = 64; off; off >>= 1) {
        if (tid < off) tmp[tid] += tmp[tid + off];
        __syncthreads();
    }
    float inv = 1.f / tmp[0];
    if (tid < 64) {
        float o = 0.f;
        #pragma unroll 8
        for (int k = 0; k < 128; k++) o += sc[k] * rows[k * 65 + tid];
        g_inter[inter_base + n * 128 + h * 64 + tid] = o * inv;
    }
}

// ---------------- agg + normsq + (cells) U ----------------
__global__ void k_agg(const float* __restrict__ W, const float* __restrict__ b,
                      const float* __restrict__ combw) {
    int n = blockIdx.x;
    __shared__ float xr[128];
    __shared__ float e[64];
    __shared__ float red[64];
    int tid = threadIdx.x;
    xr[tid] = g_inter[n * 128 + tid];
    __syncthreads();
    if (tid < 64) {
        float s = b[tid];
        #pragma unroll 8
        for (int t = 0; t < 128; t++) s += W[tid * 128 + t] * xr[t];
        g_emb[n * 64 + tid] = s;
        e[tid] = s;
        red[tid] = s * s;
    }
    __syncthreads();
    if (tid < 32) {
        float v = red[tid] + red[tid + 32];
        #pragma unroll
        for (int o = 16; o; o >>= 1) v += __shfl_down_sync(0xffffffffu, v, o);
        if (tid == 0) g_normsq[n] = v;
    }
    if (n < CELL_N) {
        float s = 0.f;
        #pragma unroll 8
        for (int j = 0; j < 64; j++) s += combw[j * 128 + tid] * e[j];
        g_U[n * 128 + tid] = s;
    }
}

// ---------------- score (blocks 0..15) + loss (block 16), one launch ----------------
__global__ void __launch_bounds__(256) k_scoreloss(
        const int* __restrict__ data, const int* __restrict__ cell_nbr,
        const int* __restrict__ drug_nbr, float* __restrict__ out, int loss_idx) {
    int blk = blockIdx.x;
    int tid = threadIdx.x;
    if (blk < 16) {
        int bidx = blk * 256 + tid;
        int c  = data[3 * bidx];
        int d1 = data[3 * bidx + 1];
        int d2 = data[3 * bidx + 2];
        const float* e1 = g_emb + (CELL_N + d1) * 64;
        const float* e2 = g_emb + (CELL_N + d2) * 64;
        const float* u  = g_U + c * 128;
        float s = 0.f;
        #pragma unroll 8
        for (int t = 0; t < 64; t++) {
            float a = e1[t], bb = e2[t];
            s += a * u[t] + bb * u[64 + t] - a * bb;
        }
        out[bidx] = s;
        return;
    }
    __shared__ float nsq[TOT_N];
    __shared__ float red[256];
    for (int i = tid; i < TOT_N; i += 256) nsq[i] = g_normsq[i];
    __syncthreads();
    float ir = 0.f;
    for (int bidx = tid; bidx < BATCH; bidx += 256) {
        int c  = data[3 * bidx];
        int d1 = data[3 * bidx + 1];
        int d2 = data[3 * bidx + 2];
        ir += nsq[c] + nsq[CELL_N + d1] + nsq[CELL_N + d2];
    }
    float nr = 0.f;
    for (int e = tid; e < 1536; e += 256) {
        int set = e >> 8, off = e & 255;
        int hop = set / 3, which = set - hop * 3;
        int nodeidx = data[hop * 3 + which];
        int p = (which == 0) ? cell_nbr[nodeidx * 256 + off] : drug_nbr[nodeidx * 256 + off];
        nr += g_tablesq[p];
    }
    red[tid] = 0.5f * ir + 0.5f * nr;
    __syncthreads();
    #pragma unroll
    for (int off = 128; off; off >>= 1) {
        if (tid < off) red[tid] += red[tid + off];
        __syncthreads();
    }
    if (tid == 0) out[loss_idx] = 1e-6f * red[0] / (float)BATCH;
}

// ---------------- launch ----------------
extern "C" void kernel_launch(void* const* d_in, const int* in_sizes, int n_in,
                              void* d_out, int out_size) {
    const int*   data     = (const int*)  d_in[0];
    const int*   cell_nbr = (const int*)  d_in[1];
    const int*   drug_nbr = (const int*)  d_in[2];
    const float* table    = (const float*)d_in[3];
    const float* cell_pre = (const float*)d_in[4];
    const float* drug_pre = (const float*)d_in[5];
    const float* c1w      = (const float*)d_in[6];
    const float* c1b      = (const float*)d_in[7];
    const float* c2w      = (const float*)d_in[8];
    const float* c2b      = (const float*)d_in[9];
    const float* ow       = (const float*)d_in[10];
    const float* ob       = (const float*)d_in[11];
    const float* aw       = (const float*)d_in[12];
    const float* ab       = (const float*)d_in[13];
    const float* cw       = (const float*)d_in[14];
    float* out = (float*)d_out;

    int tsq_blocks = (NPROT + 7) / 8;
    k_conv1<<<TSQ_BLK0 + tsq_blocks, 256>>>(cell_pre, drug_pre, c1w, c1b, table);
    k_conv2<<<TOT_N * 2, 256>>>(c2w, c2b);

    dim3 fcg(27, KSPLIT);
    k_fc<<<fcg, 256>>>(ow);
    k_fcred<<<(TOT_N * 64 + 255) / 256, 256>>>(ob);
    k_std<<<2, 1024>>>();

    k_interact<<<TOT_N * 2, 128>>>(cell_nbr, drug_nbr, table);
    k_agg<<<TOT_N, 128>>>(aw, ab, cw);
    k_scoreloss<<<17, 256>>>(data, cell_nbr, drug_nbr, out, out_size - 1);
}

// round 7
// speedup vs baseline: 1.2744x; 1.0988x over previous
#include <cuda_runtime.h>

#define CELL_N 76
#define DRUG_N 764
#define TOT_N  840
#define BATCH  4096
#define NPROT  15970
#define KSPLIT 8
#define KCHUNK 1024  // 8192 / KSPLIT
#define TSQ_N  ((NPROT + 7) / 8)   // 1997 tablesq blocks

// ---------------- scratch (device globals; no allocs allowed) ----------------
__device__ float g_pool1[TOT_N * 4 * 64 * 64];
__device__ float g_pool2[TOT_N * 8 * 32 * 32];
__device__ float g_fcp  [KSPLIT * TOT_N * 64];
__device__ float g_item [TOT_N * 64];
__device__ float g_inter[TOT_N * 128];
__device__ float g_emb  [TOT_N * 64];
__device__ float g_normsq[TOT_N];
__device__ float g_U    [CELL_N * 128];
__device__ float g_tablesq[NPROT];

// ---------------- tablesq (blocks first) + conv1 (merged cell+drug) ----------------
__global__ void __launch_bounds__(256) k_conv1(
        const float* __restrict__ cell_pre, const float* __restrict__ drug_pre,
        const float* __restrict__ w, const float* __restrict__ b,
        const float* __restrict__ table) {
    int blk = blockIdx.x;
    int tid = threadIdx.x;
    if (blk < TSQ_N) {
        int warp = blk * 8 + (tid >> 5);
        int lane = tid & 31;
        if (warp >= NPROT) return;
        const float* r = table + warp * 64;
        float a = r[lane], bb = r[lane + 32];
        float s = a * a + bb * bb;
        #pragma unroll
        for (int o = 16; o; o >>= 1) s += __shfl_down_sync(0xffffffffu, s, o);
        if (lane == 0) g_tablesq[warp] = s;
        return;
    }
    int cblk = blk - TSQ_N;
    int half = cblk & 1;
    int gn;
    const float* x;
    if (cblk < 2 * CELL_N) { gn = cblk >> 1; x = cell_pre + gn * 16384; }
    else { int n = (cblk - 2 * CELL_N) >> 1; gn = CELL_N + n; x = drug_pre + n * 16384; }
    __shared__ float tile[66 * 130];
    float wr[36];
    #pragma unroll
    for (int i = 0; i < 36; i++) wr[i] = w[i];
    float bb[4] = { b[0], b[1], b[2], b[3] };
    int row0 = half * 64 - 1;
    for (int idx = tid; idx < 66 * 130; idx += 256) {
        int r = idx / 130, c = idx - r * 130;
        int y = row0 + r, xx = c - 1;
        tile[idx] = (y >= 0 && y < 128 && (unsigned)xx < 128u) ? x[y * 128 + xx] : 0.f;
    }
    __syncthreads();
    #pragma unroll
    for (int i = 0; i < 8; i++) {
        int pos = tid + i * 256;
        int oy = pos >> 6, ox = pos & 63;
        float p[4][4];
        #pragma unroll
        for (int r = 0; r < 4; r++) {
            const float2* s = (const float2*)&tile[(2 * oy + r) * 130 + 2 * ox];
            float2 a = s[0], d = s[1];
            p[r][0] = a.x; p[r][1] = a.y; p[r][2] = d.x; p[r][3] = d.y;
        }
        #pragma unroll
        for (int oc = 0; oc < 4; oc++) {
            float q00 = bb[oc], q01 = bb[oc], q10 = bb[oc], q11 = bb[oc];
            #pragma unroll
            for (int dy = 0; dy < 3; dy++)
            #pragma unroll
            for (int dx = 0; dx < 3; dx++) {
                float wv = wr[oc * 9 + dy * 3 + dx];
                q00 += p[dy    ][dx    ] * wv;
                q01 += p[dy    ][dx + 1] * wv;
                q10 += p[dy + 1][dx    ] * wv;
                q11 += p[dy + 1][dx + 1] * wv;
            }
            float m = fmaxf(fmaxf(q00, q01), fmaxf(q10, q11));
            g_pool1[((gn * 4 + oc) * 64 + half * 32 + oy) * 64 + ox] = fmaxf(m, 0.f);
        }
    }
}

// ---------------- conv2 (4->8) + relu + pool, scalar pair-output blocking ----------------
#define C2_STR 68
#define C2_CH  (34 * C2_STR)
__global__ void __launch_bounds__(256, 3) k_conv2(
        const float* __restrict__ w, const float* __restrict__ b) {
    int n = blockIdx.x >> 1, half = blockIdx.x & 1;
    __shared__ float tile[4 * C2_CH];
    int tid = threadIdx.x;
    int row0 = half * 32 - 1;
    for (int idx = tid; idx < 4 * 34 * 66; idx += 256) {
        int c = idx / (34 * 66), rem = idx - c * (34 * 66);
        int r = rem / 66, cc = rem - r * 66;
        int y = row0 + r, xx = cc - 1;
        tile[c * C2_CH + r * C2_STR + cc] =
            ((unsigned)y < 64u && (unsigned)xx < 64u)
          ? g_pool1[((n * 4 + c) * 64 + y) * 64 + xx] : 0.f;
    }
    __syncthreads();
    int oc = tid >> 5, lane = tid & 31;
    float wr[36];
    #pragma unroll
    for (int i = 0; i < 36; i++) wr[i] = w[oc * 36 + i];
    float bs = b[oc];
    #pragma unroll
    for (int i = 0; i < 8; i++) {
        int pos = lane + i * 32;
        int oy = pos >> 4, oxp = pos & 15;
        float q[8];
        #pragma unroll
        for (int k = 0; k < 8; k++) q[k] = bs;
        #pragma unroll
        for (int c = 0; c < 4; c++) {
            float pt[4][6];
            #pragma unroll
            for (int rr = 0; rr < 4; rr++) {
                const float* base = &tile[c * C2_CH + (2 * oy + rr) * C2_STR + 4 * oxp];
                float4 a = *(const float4*)base;
                float2 b2 = *(const float2*)(base + 4);
                pt[rr][0] = a.x; pt[rr][1] = a.y; pt[rr][2] = a.z;
                pt[rr][3] = a.w; pt[rr][4] = b2.x; pt[rr][5] = b2.y;
            }
            #pragma unroll
            for (int dy = 0; dy < 3; dy++)
            #pragma unroll
            for (int dx = 0; dx < 3; dx++) {
                float wv = wr[c * 9 + dy * 3 + dx];
                q[0] += pt[dy    ][dx    ] * wv;
                q[1] += pt[dy    ][dx + 1] * wv;
                q[2] += pt[dy + 1][dx    ] * wv;
                q[3] += pt[dy + 1][dx + 1] * wv;
                q[4] += pt[dy    ][dx + 2] * wv;
                q[5] += pt[dy    ][dx + 3] * wv;
                q[6] += pt[dy + 1][dx + 2] * wv;
                q[7] += pt[dy + 1][dx + 3] * wv;
            }
        }
        float m0 = fmaxf(fmaxf(q[0], q[1]), fmaxf(q[2], q[3]));
        float m1 = fmaxf(fmaxf(q[4], q[5]), fmaxf(q[6], q[7]));
        float2 v = make_float2(fmaxf(m0, 0.f), fmaxf(m1, 0.f));
        *(float2*)&g_pool2[((n * 8 + oc) * 32 + half * 16 + oy) * 32 + 2 * oxp] = v;
    }
}

// ---------------- FC as tiled GEMM with K-split ----------------
__global__ void __launch_bounds__(256) k_fc(const float* __restrict__ W) {
    int m0 = blockIdx.x * 32;
    int kb = blockIdx.y;
    int k0 = kb * KCHUNK;
    __shared__ float Xs[32][64];
    __shared__ float Ws[64][68];
    int tid = threadIdx.x;
    int tm = tid >> 5, tn = tid & 31;
    float acc[4][2] = {};
    for (int kt = 0; kt < KCHUNK; kt += 64) {
        #pragma unroll
        for (int i = 0; i < 8; i++) {
            int idx = tid + i * 256;
            int r = idx >> 6, c = idx & 63;
            int m = m0 + r;
            Xs[r][c] = (m < TOT_N) ? g_pool2[m * 8192 + k0 + kt + c] : 0.f;
        }
        #pragma unroll
        for (int i = 0; i < 16; i++) {
            int idx = tid + i * 256;
            int j = idx >> 6, c = idx & 63;
            Ws[j][c] = W[j * 8192 + k0 + kt + c];
        }
        __syncthreads();
        #pragma unroll
        for (int kk = 0; kk < 64; kk += 4) {
            float4 w0 = *(const float4*)&Ws[tn     ][kk];
            float4 w1 = *(const float4*)&Ws[tn + 32][kk];
            #pragma unroll
            for (int r = 0; r < 4; r++) {
                float4 xv = *(const float4*)&Xs[tm * 4 + r][kk];
                acc[r][0] += xv.x * w0.x + xv.y * w0.y + xv.z * w0.z + xv.w * w0.w;
                acc[r][1] += xv.x * w1.x + xv.y * w1.y + xv.z * w1.z + xv.w * w1.w;
            }
        }
        __syncthreads();
    }
    #pragma unroll
    for (int r = 0; r < 4; r++) {
        int m = m0 + tm * 4 + r;
        if (m < TOT_N) {
            g_fcp[(kb * TOT_N + m) * 64 + tn     ] = acc[r][0];
            g_fcp[(kb * TOT_N + m) * 64 + tn + 32] = acc[r][1];
        }
    }
}

// ---------------- reduce K-split partials + bias -> g_item (wide grid) ----------------
__global__ void k_fcred(const float* __restrict__ b) {
    int idx = blockIdx.x * blockDim.x + threadIdx.x;
    if (idx >= TOT_N * 64) return;
    float s = b[idx & 63];
    #pragma unroll
    for (int kb = 0; kb < KSPLIT; kb++) s += g_fcp[kb * TOT_N * 64 + idx];
    g_item[idx] = s;
}

// ---------------- standardize: compile-time N, 2 passes ----------------
template<int ROW0, int N>
__device__ __forceinline__ void std_body(float2* red, float* mv, float* sv) {
    int tid = threadIdx.x;
    int j = tid & 63, q = tid >> 6;
    constexpr int R = (N + 15) / 16;
    float s = 0.f, ss = 0.f;
    #pragma unroll
    for (int i = 0; i < R; i++) {
        int n = q + i * 16;
        if (n < N) {
            float v = g_item[(ROW0 + n) * 64 + j];
            s += v;
            ss += v * v;
        }
    }
    red[tid] = make_float2(s, ss);
    __syncthreads();
    if (tid < 64) {
        float S = 0.f, SS = 0.f;
        #pragma unroll
        for (int k = 0; k < 16; k++) {
            float2 r = red[tid + 64 * k];
            S += r.x; SS += r.y;
        }
        float m = S / (float)N;
        float var = (SS - (float)N * m * m) / (float)(N - 1);
        mv[tid] = m;
        sv[tid] = rsqrtf(var);
    }
    __syncthreads();
    float mean = mv[j], inv = sv[j];
    #pragma unroll
    for (int i = 0; i < R; i++) {
        int n = q + i * 16;
        if (n < N) {
            int row = ROW0 + n;
            g_item[row * 64 + j] = (g_item[row * 64 + j] - mean) * inv;
        }
    }
}

__global__ void __launch_bounds__(1024) k_std() {
    __shared__ float2 red[1024];
    __shared__ float mv[64];
    __shared__ float sv[64];
    if (blockIdx.x == 0) std_body<0, CELL_N>(red, mv, sv);
    else                 std_body<CELL_N, DRUG_N>(red, mv, sv);
}

// ---------------- interact: shfl reductions + k-split phase B ----------------
__global__ void k_interact(const int* __restrict__ cell_nbr, const int* __restrict__ drug_nbr,
                           const float* __restrict__ table) {
    int blk = blockIdx.x;
    const int* nbr;
    int nh, item_base, inter_base;
    if (blk < 2 * CELL_N) { nbr = cell_nbr; nh = blk; item_base = 0; inter_base = 0; }
    else { nbr = drug_nbr; nh = blk - 2 * CELL_N; item_base = CELL_N * 64; inter_base = CELL_N * 128; }
    int n = nh >> 1, h = nh & 1;
    __shared__ float rows[128 * 65];
    __shared__ float it[64];
    __shared__ int   idxs[128];
    __shared__ float sc[128];
    __shared__ float wred[8];
    __shared__ float part[128];
    int tid = threadIdx.x;
    int warp = tid >> 5, lane = tid & 31;
    idxs[tid] = nbr[nh * 128 + tid];
    if (tid < 64) it[tid] = g_item[item_base + n * 64 + tid];
    __syncthreads();
    for (int e = tid; e < 128 * 64; e += 128) {
        int k = e >> 6, d = e & 63;
        rows[k * 65 + d] = table[idxs[k] * 64 + d];
    }
    __syncthreads();
    // phase A: one dot per thread
    float s = 0.f;
    #pragma unroll 8
    for (int d = 0; d < 64; d++) s += rows[tid * 65 + d] * it[d];
    // block max via shfl
    float m = s;
    #pragma unroll
    for (int o = 16; o; o >>= 1) m = fmaxf(m, __shfl_xor_sync(0xffffffffu, m, o));
    if (lane == 0) wred[warp] = m;
    __syncthreads();
    float mx = fmaxf(fmaxf(wred[0], wred[1]), fmaxf(wred[2], wred[3]));
    float e = expf(s - mx);
    sc[tid] = e;
    float t = e;
    #pragma unroll
    for (int o = 16; o; o >>= 1) t += __shfl_xor_sync(0xffffffffu, t, o);
    if (lane == 0) wred[4 + warp] = t;
    __syncthreads();
    float inv = 1.f / (wred[4] + wred[5] + wred[6] + wred[7]);
    // phase B: k-split over 2 halves, all 128 threads active
    int d = tid & 63, kh = tid >> 6;
    float o = 0.f;
    int kb = kh * 64;
    #pragma unroll 8
    for (int k2 = 0; k2 < 64; k2++) {
        int k = kb + k2;
        o += sc[k] * rows[k * 65 + d];
    }
    part[tid] = o;
    __syncthreads();
    if (tid < 64)
        g_inter[inter_base + n * 128 + h * 64 + tid] = (part[tid] + part[tid + 64]) * inv;
}

// ---------------- agg (k-split) + normsq + (cells) U ----------------
__global__ void k_agg(const float* __restrict__ W, const float* __restrict__ b,
                      const float* __restrict__ combw) {
    int n = blockIdx.x;
    __shared__ float xr[128];
    __shared__ float e[64];
    __shared__ float red[64];
    __shared__ float part[128];
    int tid = threadIdx.x;
    xr[tid] = g_inter[n * 128 + tid];
    __syncthreads();
    int j = tid & 63, kh = tid >> 6;
    float s = 0.f;
    int tb = kh * 64;
    #pragma unroll 8
    for (int t2 = 0; t2 < 64; t2++) {
        int t = tb + t2;
        s += W[j * 128 + t] * xr[t];
    }
    part[tid] = s;
    __syncthreads();
    if (tid < 64) {
        float v = part[tid] + part[tid + 64] + b[tid];
        g_emb[n * 64 + tid] = v;
        e[tid] = v;
        red[tid] = v * v;
    }
    __syncthreads();
    if (tid < 32) {
        float v = red[tid] + red[tid + 32];
        #pragma unroll
        for (int o = 16; o; o >>= 1) v += __shfl_down_sync(0xffffffffu, v, o);
        if (tid == 0) g_normsq[n] = v;
    }
    if (n < CELL_N) {
        float s2 = 0.f;
        #pragma unroll 8
        for (int j2 = 0; j2 < 64; j2++) s2 += combw[j2 * 128 + tid] * e[j2];
        g_U[n * 128 + tid] = s2;
    }
}

// ---------------- score (blocks 0..15) + loss (block 16), one launch ----------------
__global__ void __launch_bounds__(256) k_scoreloss(
        const int* __restrict__ data, const int* __restrict__ cell_nbr,
        const int* __restrict__ drug_nbr, float* __restrict__ out, int loss_idx) {
    int blk = blockIdx.x;
    int tid = threadIdx.x;
    if (blk < 16) {
        int bidx = blk * 256 + tid;
        int c  = data[3 * bidx];
        int d1 = data[3 * bidx + 1];
        int d2 = data[3 * bidx + 2];
        const float* e1 = g_emb + (CELL_N + d1) * 64;
        const float* e2 = g_emb + (CELL_N + d2) * 64;
        const float* u  = g_U + c * 128;
        float s = 0.f;
        #pragma unroll 8
        for (int t = 0; t < 64; t++) {
            float a = e1[t], bb = e2[t];
            s += a * u[t] + bb * u[64 + t] - a * bb;
        }
        out[bidx] = s;
        return;
    }
    __shared__ float nsq[TOT_N];
    __shared__ float red[256];
    for (int i = tid; i < TOT_N; i += 256) nsq[i] = g_normsq[i];
    __syncthreads();
    float ir = 0.f;
    for (int bidx = tid; bidx < BATCH; bidx += 256) {
        int c  = data[3 * bidx];
        int d1 = data[3 * bidx + 1];
        int d2 = data[3 * bidx + 2];
        ir += nsq[c] + nsq[CELL_N + d1] + nsq[CELL_N + d2];
    }
    float nr = 0.f;
    for (int e = tid; e < 1536; e += 256) {
        int set = e >> 8, off = e & 255;
        int hop = set / 3, which = set - hop * 3;
        int nodeidx = data[hop * 3 + which];
        int p = (which == 0) ? cell_nbr[nodeidx * 256 + off] : drug_nbr[nodeidx * 256 + off];
        nr += g_tablesq[p];
    }
    red[tid] = 0.5f * ir + 0.5f * nr;
    __syncthreads();
    #pragma unroll
    for (int off = 128; off; off >>= 1) {
        if (tid < off) red[tid] += red[tid + off];
        __syncthreads();
    }
    if (tid == 0) out[loss_idx] = 1e-6f * red[0] / (float)BATCH;
}

// ---------------- launch ----------------
extern "C" void kernel_launch(void* const* d_in, const int* in_sizes, int n_in,
                              void* d_out, int out_size) {
    const int*   data     = (const int*)  d_in[0];
    const int*   cell_nbr = (const int*)  d_in[1];
    const int*   drug_nbr = (const int*)  d_in[2];
    const float* table    = (const float*)d_in[3];
    const float* cell_pre = (const float*)d_in[4];
    const float* drug_pre = (const float*)d_in[5];
    const float* c1w      = (const float*)d_in[6];
    const float* c1b      = (const float*)d_in[7];
    const float* c2w      = (const float*)d_in[8];
    const float* c2b      = (const float*)d_in[9];
    const float* ow       = (const float*)d_in[10];
    const float* ob       = (const float*)d_in[11];
    const float* aw       = (const float*)d_in[12];
    const float* ab       = (const float*)d_in[13];
    const float* cw       = (const float*)d_in[14];
    float* out = (float*)d_out;

    k_conv1<<<TSQ_N + TOT_N * 2, 256>>>(cell_pre, drug_pre, c1w, c1b, table);
    k_conv2<<<TOT_N * 2, 256>>>(c2w, c2b);

    dim3 fcg(27, KSPLIT);
    k_fc<<<fcg, 256>>>(ow);
    k_fcred<<<(TOT_N * 64 + 255) / 256, 256>>>(ob);
    k_std<<<2, 1024>>>();

    k_interact<<<TOT_N * 2, 128>>>(cell_nbr, drug_nbr, table);
    k_agg<<<TOT_N, 128>>>(aw, ab, cw);
    k_scoreloss<<<17, 256>>>(data, cell_nbr, drug_nbr, out, out_size - 1);
}